// round 6
// baseline (speedup 1.0000x reference)
#include <cuda_runtime.h>
#include <cstdint>
#include <math.h>

#define S_LEN 2048
#define B_SZ  32
#define D_SZ  512
#define KCONV 147
#define PADC  73
#define NS    32                 // s-splits
#define ROWS_PB 64               // rows per block
#define ROWS_PW 8                // rows per warp
#define NSLOT 4                  // per-warp ring depth
#define KSPL  4                  // gemm k-splits

// ---------------- scratch ----------------
__device__ float g_attp[KSPL][B_SZ * D_SZ];  // GEMM k-split partials
__device__ float g_c  [B_SZ * S_LEN];        // adj * exp(w)
__device__ float g_pz [B_SZ * NS];           // per-split sum of c
__device__ float g_pacc[B_SZ * NS * D_SZ];   // per-split weighted sums
__device__ int   g_done[B_SZ];               // per-batch arrival counters

__device__ __forceinline__ void cp16(unsigned int s, const void* g) {
    asm volatile("cp.async.cg.shared.global [%0], [%1], 16;\n" :: "r"(s), "l"(g) : "memory");
}
__device__ __forceinline__ void cp_commit() {
    asm volatile("cp.async.commit_group;\n" ::: "memory");
}
template <int N>
__device__ __forceinline__ void cp_wait() {
    asm volatile("cp.async.wait_group %0;\n" :: "n"(N) : "memory");
}

// ---------------- kernel 1: attended = state @ W^T (k-split x4) ----------
__global__ __launch_bounds__(256) void k_gemm(const float* __restrict__ state,
                                              const float* __restrict__ W) {
    __shared__ float st[128][33];
    __shared__ float ws[8][128];
    const int tid  = threadIdx.x;
    const int lane = tid & 31;      // batch
    const int wid  = tid >> 5;      // one of 8 d's
    const int gx   = blockIdx.x, gy = blockIdx.y;
    const int k0   = gy * 128;
    const int d    = gx * 8 + wid;

    if (gx == 0 && gy == 0 && tid < B_SZ) g_done[tid] = 0;

    for (int i = tid; i < 32 * 128; i += 256) {
        int b = i >> 7, kk = i & 127;
        st[kk][b] = state[b * D_SZ + k0 + kk];
    }
    for (int i = tid; i < 8 * 128; i += 256) {
        int dd = i >> 7, kk = i & 127;
        ws[dd][kk] = W[(gx * 8 + dd) * D_SZ + k0 + kk];
    }
    __syncthreads();

    float a0 = 0.f, a1 = 0.f, a2 = 0.f, a3 = 0.f;
#pragma unroll 8
    for (int kk = 0; kk < 128; kk += 4) {
        a0 = fmaf(st[kk + 0][lane], ws[wid][kk + 0], a0);
        a1 = fmaf(st[kk + 1][lane], ws[wid][kk + 1], a1);
        a2 = fmaf(st[kk + 2][lane], ws[wid][kk + 2], a2);
        a3 = fmaf(st[kk + 3][lane], ws[wid][kk + 3], a3);
    }
    g_attp[gy][lane * D_SZ + d] = (a0 + a1) + (a2 + a3);
}

// ---------------- kernel 2: cp.async 4-deep pipelined main pass -----------
// grid (B_SZ, NS); 256 threads = 8 warps. Each warp streams 8 rows through a
// private 4-slot dynamic-smem ring; no cross-warp sync in the hot loop.
__global__ __launch_bounds__(256) void k_main(const float* __restrict__ enc,
                                              const float* __restrict__ b_att,
                                              const float* __restrict__ prev,
                                              const float* __restrict__ cw,
                                              const float* __restrict__ cb,
                                              float* __restrict__ out) {
    extern __shared__ float4 s_ring[];              // [8][NSLOT][128] = 64 KB
    __shared__ float  s_spc[ROWS_PB + 2 * PADC];
    __shared__ float  s_cw[KCONV];
    __shared__ float  s_scs[8];
    __shared__ float  s_invZ;
    __shared__ int    s_last;

    const int b   = blockIdx.x;
    const int sp  = blockIdx.y;
    const int tid = threadIdx.x, lane = tid & 31, w = tid >> 5;

    const int sbase = sp * ROWS_PB + w * ROWS_PW;
    const char* gbase = (const char*)enc;

    const unsigned int ring0 =
        (unsigned int)__cvta_generic_to_shared(s_ring + (size_t)w * NSLOT * 128);

    // ---- cp.async prologue: rows 0..3 ----
#pragma unroll
    for (int r = 0; r < NSLOT; r++) {
        const char* g = gbase + ((size_t)(sbase + r) * B_SZ + b) * (D_SZ * 4);
        unsigned int sa = ring0 + r * 2048;
#pragma unroll
        for (int k = 0; k < 4; k++)
            cp16(sa + (k * 32 + lane) * 16, g + (k * 32 + lane) * 16);
        cp_commit();
    }

    // ---- stage conv inputs (overlaps the async loads) ----
    if (tid < KCONV) s_cw[tid] = cw[tid];
    {
        const int c0 = sp * ROWS_PB;
        for (int i = tid; i < ROWS_PB + 2 * PADC; i += 256) {
            int s = c0 + i - PADC;
            s_spc[i] = (s >= 0 && s < S_LEN) ? prev[b * S_LEN + s] : 0.f;
        }
    }

    // ---- normalized attended state (per warp, redundant) ----
    const float4* ba4 = reinterpret_cast<const float4*>(b_att);
    float4 n0, n1, n2, n3;
    {
        float4 a0, a1, a2, a3, t;
#define LD_AT(q, dst) \
        dst = ba4[(q) * 32 + lane]; \
        _Pragma("unroll") \
        for (int p_ = 0; p_ < KSPL; p_++) { \
            t = reinterpret_cast<const float4*>(g_attp[p_])[b * 128 + (q) * 32 + lane]; \
            dst.x += t.x; dst.y += t.y; dst.z += t.z; dst.w += t.w; \
        }
        LD_AT(0, a0) LD_AT(1, a1) LD_AT(2, a2) LD_AT(3, a3)
#undef LD_AT
        float ss = a0.x*a0.x + a0.y*a0.y + a0.z*a0.z + a0.w*a0.w
                 + a1.x*a1.x + a1.y*a1.y + a1.z*a1.z + a1.w*a1.w
                 + a2.x*a2.x + a2.y*a2.y + a2.z*a2.z + a2.w*a2.w
                 + a3.x*a3.x + a3.y*a3.y + a3.z*a3.z + a3.w*a3.w;
#pragma unroll
        for (int o = 16; o; o >>= 1) ss += __shfl_xor_sync(0xffffffffu, ss, o);
        float inv = (ss > 0.f) ? rsqrtf(ss) : 1e10f;
        n0.x=a0.x*inv; n0.y=a0.y*inv; n0.z=a0.z*inv; n0.w=a0.w*inv;
        n1.x=a1.x*inv; n1.y=a1.y*inv; n1.z=a1.z*inv; n1.w=a1.w*inv;
        n2.x=a2.x*inv; n2.y=a2.y*inv; n2.z=a2.z*inv; n2.w=a2.w*inv;
        n3.x=a3.x*inv; n3.y=a3.y*inv; n3.z=a3.z*inv; n3.w=a3.w*inv;
    }
    __syncthreads();   // s_spc / s_cw ready

    // ---- conv: each warp produces its own 8 adj values (quad split) ----
    float vfull;
    {
        const int o_ = tid >> 2, q = tid & 3;
        const int j0 = q * 37, cnt = (q < 3) ? 37 : 36;
        float a = 0.f, a2 = 0.f;
        for (int j = 0; j < cnt - 1; j += 2) {
            a  = fmaf(s_spc[o_ + j0 + j],     s_cw[j0 + j],     a);
            a2 = fmaf(s_spc[o_ + j0 + j + 1], s_cw[j0 + j + 1], a2);
        }
        if (cnt & 1) a = fmaf(s_spc[o_ + j0 + cnt - 1], s_cw[j0 + cnt - 1], a);
        vfull = a + a2;
        vfull += __shfl_xor_sync(0xffffffffu, vfull, 1);
        vfull += __shfl_xor_sync(0xffffffffu, vfull, 2);
    }
    const float cb0 = __ldg(cb);

    // ---- main pipelined loop: 8 rows/warp, 3 rows in flight ----
    float4 acc0 = make_float4(0,0,0,0), acc1 = acc0, acc2 = acc0, acc3 = acc0;
    float csum = 0.f;

#pragma unroll
    for (int r = 0; r < ROWS_PW; r++) {
        cp_wait<NSLOT - 1>();     // group g <-> row g; row r landed
        __syncwarp();

        const float4* rowp = s_ring + ((size_t)w * NSLOT + (r & (NSLOT - 1))) * 128;
        float4 e0 = rowp[0 * 32 + lane];
        float4 e1 = rowp[1 * 32 + lane];
        float4 e2 = rowp[2 * 32 + lane];
        float4 e3 = rowp[3 * 32 + lane];

        // refill this slot with row r+NSLOT
        if (r + NSLOT < ROWS_PW) {
            const char* g = gbase + ((size_t)(sbase + r + NSLOT) * B_SZ + b) * (D_SZ * 4);
            unsigned int sa = ring0 + (r & (NSLOT - 1)) * 2048;
#pragma unroll
            for (int k = 0; k < 4; k++)
                cp16(sa + (k * 32 + lane) * 16, g + (k * 32 + lane) * 16);
        }
        cp_commit();              // keep group count in lockstep

        float dot = e0.x*n0.x + e0.y*n0.y + e0.z*n0.z + e0.w*n0.w
                  + e1.x*n1.x + e1.y*n1.y + e1.z*n1.z + e1.w*n1.w
                  + e2.x*n2.x + e2.y*n2.y + e2.z*n2.z + e2.w*n2.w
                  + e3.x*n3.x + e3.y*n3.y + e3.z*n3.z + e3.w*n3.w;
        float ss  = e0.x*e0.x + e0.y*e0.y + e0.z*e0.z + e0.w*e0.w
                  + e1.x*e1.x + e1.y*e1.y + e1.z*e1.z + e1.w*e1.w
                  + e2.x*e2.x + e2.y*e2.y + e2.z*e2.z + e2.w*e2.w
                  + e3.x*e3.x + e3.y*e3.y + e3.z*e3.z + e3.w*e3.w;
#pragma unroll
        for (int o = 16; o; o >>= 1) {
            dot += __shfl_xor_sync(0xffffffffu, dot, o);
            ss  += __shfl_xor_sync(0xffffffffu, ss,  o);
        }
        float wt = dot * ((ss > 0.f) ? rsqrtf(ss) : 1e10f);   // |wt| <= 1
        float adjr = fmaxf(__shfl_sync(0xffffffffu, vfull, r << 2) + cb0, 0.f);
        float c = adjr * __expf(wt);
        if (lane == 0) g_c[b * S_LEN + sbase + r] = c;
        csum += c;
        acc0.x = fmaf(c, e0.x, acc0.x); acc0.y = fmaf(c, e0.y, acc0.y);
        acc0.z = fmaf(c, e0.z, acc0.z); acc0.w = fmaf(c, e0.w, acc0.w);
        acc1.x = fmaf(c, e1.x, acc1.x); acc1.y = fmaf(c, e1.y, acc1.y);
        acc1.z = fmaf(c, e1.z, acc1.z); acc1.w = fmaf(c, e1.w, acc1.w);
        acc2.x = fmaf(c, e2.x, acc2.x); acc2.y = fmaf(c, e2.y, acc2.y);
        acc2.z = fmaf(c, e2.z, acc2.z); acc2.w = fmaf(c, e2.w, acc2.w);
        acc3.x = fmaf(c, e3.x, acc3.x); acc3.y = fmaf(c, e3.y, acc3.y);
        acc3.z = fmaf(c, e3.z, acc3.z); acc3.w = fmaf(c, e3.w, acc3.w);
    }

    // ---- block combine (reuse the ring) ----
    __syncthreads();
    float4* sacc = s_ring;
    sacc[w * 128 + 0 * 32 + lane] = acc0;
    sacc[w * 128 + 1 * 32 + lane] = acc1;
    sacc[w * 128 + 2 * 32 + lane] = acc2;
    sacc[w * 128 + 3 * 32 + lane] = acc3;
    if (lane == 0) s_scs[w] = csum;
    __syncthreads();

    if (tid < 128) {
        float4 v = sacc[tid];
#pragma unroll
        for (int p = 1; p < 8; p++) {
            float4 u = sacc[p * 128 + tid];
            v.x += u.x; v.y += u.y; v.z += u.z; v.w += u.w;
        }
        reinterpret_cast<float4*>(g_pacc)[(b * NS + sp) * 128 + tid] = v;
    }
    if (tid == 0) {
        float z = 0.f;
#pragma unroll
        for (int p = 0; p < 8; p++) z += s_scs[p];
        g_pz[b * NS + sp] = z;
    }

    // ---- last block per batch finalizes ----
    __threadfence();
    __syncthreads();
    if (tid == 0) {
        int v = atomicAdd(&g_done[b], 1);
        s_last = (v == NS - 1);
    }
    __syncthreads();
    if (!s_last) return;
    __threadfence();

    if (tid == 0) {
        float Z = 0.f;
#pragma unroll
        for (int p = 0; p < NS; p++) Z += __ldcg(&g_pz[b * NS + p]);
        s_invZ = 1.f / Z;
    }
    __syncthreads();
    const float invZ = s_invZ;

    float2 s2 = make_float2(0.f, 0.f);
    const float2* pacc2 = reinterpret_cast<const float2*>(g_pacc);
#pragma unroll
    for (int p = 0; p < NS; p++) {
        float2 v = __ldcg(&pacc2[(b * NS + p) * 256 + tid]);
        s2.x += v.x; s2.y += v.y;
    }
    float2 o2; o2.x = s2.x * invZ; o2.y = s2.y * invZ;
    reinterpret_cast<float2*>(out)[b * 256 + tid] = o2;

    for (int s = tid; s < S_LEN; s += 256)
        out[B_SZ * D_SZ + b * S_LEN + s] = __ldcg(&g_c[b * S_LEN + s]) * invZ;
}

// ---------------- launch ----------------
extern "C" void kernel_launch(void* const* d_in, const int* in_sizes, int n_in,
                              void* d_out, int out_size) {
    const float* enc   = (const float*)d_in[0];
    const float* state = (const float*)d_in[1];
    const float* prev  = (const float*)d_in[2];
    const float* W     = (const float*)d_in[3];
    const float* batt  = (const float*)d_in[4];
    const float* cw    = (const float*)d_in[5];
    const float* cb    = (const float*)d_in[6];
    float* out = (float*)d_out;

    const int ring_bytes = 8 * NSLOT * 128 * sizeof(float4);   // 65536
    cudaFuncSetAttribute(k_main, cudaFuncAttributeMaxDynamicSharedMemorySize,
                         ring_bytes);

    k_gemm<<<dim3(64, KSPL), 256>>>(state, W);
    k_main<<<dim3(B_SZ, NS), 256, ring_bytes>>>(enc, batt, prev, cw, cb, out);
}

// round 8
// speedup vs baseline: 1.0762x; 1.0762x over previous
#include <cuda_runtime.h>
#include <cstdint>
#include <math.h>

#define S_LEN 2048
#define B_SZ  32
#define D_SZ  512
#define KCONV 147
#define PADC  73
#define NS    32                 // s-splits
#define ROWS_PB 64               // rows per block
#define ROWS_PW 8                // rows per warp
#define NSLOT 2                  // per-warp ring depth
#define KSPL  4                  // gemm k-splits

// ---------------- scratch ----------------
__device__ float g_attp[KSPL][B_SZ * D_SZ];  // GEMM k-split partials
__device__ float g_c  [B_SZ * S_LEN];        // adj * exp(w)
__device__ float g_pz [B_SZ * NS];           // per-split sum of c
__device__ float g_pacc[B_SZ * NS * D_SZ];   // per-split weighted sums
__device__ int   g_done[B_SZ];               // per-batch arrival counters

__device__ __forceinline__ void cp16(unsigned int s, const void* g) {
    asm volatile("cp.async.cg.shared.global [%0], [%1], 16;\n" :: "r"(s), "l"(g) : "memory");
}
__device__ __forceinline__ void cp_commit() {
    asm volatile("cp.async.commit_group;\n" ::: "memory");
}
template <int N>
__device__ __forceinline__ void cp_wait() {
    asm volatile("cp.async.wait_group %0;\n" :: "n"(N) : "memory");
}

// ---------------- kernel 1: attended = state @ W^T (k-split x4) ----------
__global__ __launch_bounds__(256) void k_gemm(const float* __restrict__ state,
                                              const float* __restrict__ W) {
    __shared__ float st[128][33];
    __shared__ float ws[8][128];
    const int tid  = threadIdx.x;
    const int lane = tid & 31;      // batch
    const int wid  = tid >> 5;      // one of 8 d's
    const int gx   = blockIdx.x, gy = blockIdx.y;
    const int k0   = gy * 128;
    const int d    = gx * 8 + wid;

    if (gx == 0 && gy == 0 && tid < B_SZ) g_done[tid] = 0;

    for (int i = tid; i < 32 * 128; i += 256) {
        int b = i >> 7, kk = i & 127;
        st[kk][b] = state[b * D_SZ + k0 + kk];
    }
    for (int i = tid; i < 8 * 128; i += 256) {
        int dd = i >> 7, kk = i & 127;
        ws[dd][kk] = W[(gx * 8 + dd) * D_SZ + k0 + kk];
    }
    __syncthreads();

    float a0 = 0.f, a1 = 0.f, a2 = 0.f, a3 = 0.f;
#pragma unroll 8
    for (int kk = 0; kk < 128; kk += 4) {
        a0 = fmaf(st[kk + 0][lane], ws[wid][kk + 0], a0);
        a1 = fmaf(st[kk + 1][lane], ws[wid][kk + 1], a1);
        a2 = fmaf(st[kk + 2][lane], ws[wid][kk + 2], a2);
        a3 = fmaf(st[kk + 3][lane], ws[wid][kk + 3], a3);
    }
    g_attp[gy][lane * D_SZ + d] = (a0 + a1) + (a2 + a3);
}

// ---------------- kernel 2: high-occupancy cp.async main pass -------------
// grid (B_SZ, NS); 256 threads = 8 warps; 4 blocks/SM (regs<=64, 36KB smem).
__global__ __launch_bounds__(256, 4) void k_main(const float* __restrict__ enc,
                                                 const float* __restrict__ b_att,
                                                 const float* __restrict__ prev,
                                                 const float* __restrict__ cw,
                                                 const float* __restrict__ cb,
                                                 float* __restrict__ out) {
    __shared__ float4 s_ring[8][NSLOT][128];        // 32 KB row ring
    __shared__ float4 s_ns[128];                    // normalized attended state
    __shared__ float  s_spc[ROWS_PB + 2 * PADC];
    __shared__ float  s_cw[KCONV];
    __shared__ float  s_scs[8];
    __shared__ float  s_invZ;
    __shared__ int    s_last;

    const int b   = blockIdx.x;
    const int sp  = blockIdx.y;
    const int tid = threadIdx.x, lane = tid & 31, w = tid >> 5;

    const int sbase = sp * ROWS_PB + w * ROWS_PW;
    const char* gbase = (const char*)enc;

    const unsigned int ring0 =
        (unsigned int)__cvta_generic_to_shared(&s_ring[w][0][0]);

    // ---- cp.async prologue: rows 0,1 per warp ----
#pragma unroll
    for (int r = 0; r < NSLOT; r++) {
        const char* g = gbase + ((size_t)(sbase + r) * B_SZ + b) * (D_SZ * 4);
        unsigned int sa = ring0 + r * 2048;
#pragma unroll
        for (int k = 0; k < 4; k++)
            cp16(sa + (k * 32 + lane) * 16, g + (k * 32 + lane) * 16);
        cp_commit();
    }

    // ---- stage conv inputs (overlaps async loads) ----
    if (tid < KCONV) s_cw[tid] = cw[tid];
    {
        const int c0 = sp * ROWS_PB;
        for (int i = tid; i < ROWS_PB + 2 * PADC; i += 256) {
            int s = c0 + i - PADC;
            s_spc[i] = (s >= 0 && s < S_LEN) ? prev[b * S_LEN + s] : 0.f;
        }
    }

    // ---- warp 0 computes normalized attended state into s_ns ----
    if (w == 0) {
        const float4* ba4 = reinterpret_cast<const float4*>(b_att);
        float4 a0, a1, a2, a3, t;
#define LD_AT(q, dst) \
        dst = ba4[(q) * 32 + lane]; \
        _Pragma("unroll") \
        for (int p_ = 0; p_ < KSPL; p_++) { \
            t = reinterpret_cast<const float4*>(g_attp[p_])[b * 128 + (q) * 32 + lane]; \
            dst.x += t.x; dst.y += t.y; dst.z += t.z; dst.w += t.w; \
        }
        LD_AT(0, a0) LD_AT(1, a1) LD_AT(2, a2) LD_AT(3, a3)
#undef LD_AT
        float ss = a0.x*a0.x + a0.y*a0.y + a0.z*a0.z + a0.w*a0.w
                 + a1.x*a1.x + a1.y*a1.y + a1.z*a1.z + a1.w*a1.w
                 + a2.x*a2.x + a2.y*a2.y + a2.z*a2.z + a2.w*a2.w
                 + a3.x*a3.x + a3.y*a3.y + a3.z*a3.z + a3.w*a3.w;
#pragma unroll
        for (int o = 16; o; o >>= 1) ss += __shfl_xor_sync(0xffffffffu, ss, o);
        float inv = (ss > 0.f) ? rsqrtf(ss) : 1e10f;
        a0.x*=inv; a0.y*=inv; a0.z*=inv; a0.w*=inv;
        a1.x*=inv; a1.y*=inv; a1.z*=inv; a1.w*=inv;
        a2.x*=inv; a2.y*=inv; a2.z*=inv; a2.w*=inv;
        a3.x*=inv; a3.y*=inv; a3.z*=inv; a3.w*=inv;
        s_ns[0*32 + lane] = a0;
        s_ns[1*32 + lane] = a1;
        s_ns[2*32 + lane] = a2;
        s_ns[3*32 + lane] = a3;
    }
    __syncthreads();   // s_spc / s_cw / s_ns ready

    // ---- conv: each warp produces its own 8 adj values (quad split) ----
    float vfull;
    {
        const int o_ = tid >> 2, q = tid & 3;
        const int j0 = q * 37, cnt = (q < 3) ? 37 : 36;
        float a = 0.f, a2 = 0.f;
        for (int j = 0; j < cnt - 1; j += 2) {
            a  = fmaf(s_spc[o_ + j0 + j],     s_cw[j0 + j],     a);
            a2 = fmaf(s_spc[o_ + j0 + j + 1], s_cw[j0 + j + 1], a2);
        }
        if (cnt & 1) a = fmaf(s_spc[o_ + j0 + cnt - 1], s_cw[j0 + cnt - 1], a);
        vfull = a + a2;
        vfull += __shfl_xor_sync(0xffffffffu, vfull, 1);
        vfull += __shfl_xor_sync(0xffffffffu, vfull, 2);
    }
    const float cb0 = __ldg(cb);

    // ---- main loop: 8 rows/warp ----
    float4 acc0 = make_float4(0,0,0,0), acc1 = acc0, acc2 = acc0, acc3 = acc0;
    float csum = 0.f;

#pragma unroll
    for (int r = 0; r < ROWS_PW; r++) {
        cp_wait<NSLOT - 1>();
        __syncwarp();

        const float4* rowp = &s_ring[w][r & (NSLOT - 1)][0];
        float4 e0 = rowp[0 * 32 + lane];
        float4 e1 = rowp[1 * 32 + lane];
        float4 e2 = rowp[2 * 32 + lane];
        float4 e3 = rowp[3 * 32 + lane];

        if (r + NSLOT < ROWS_PW) {
            const char* g = gbase + ((size_t)(sbase + r + NSLOT) * B_SZ + b) * (D_SZ * 4);
            unsigned int sa = ring0 + (r & (NSLOT - 1)) * 2048;
#pragma unroll
            for (int k = 0; k < 4; k++)
                cp16(sa + (k * 32 + lane) * 16, g + (k * 32 + lane) * 16);
        }
        cp_commit();

        // dot & sumsq; ns streamed from smem (short live ranges)
        float dot, ss;
        {
            float4 nv = s_ns[0 * 32 + lane];
            dot = e0.x*nv.x + e0.y*nv.y + e0.z*nv.z + e0.w*nv.w;
            ss  = e0.x*e0.x + e0.y*e0.y + e0.z*e0.z + e0.w*e0.w;
            nv = s_ns[1 * 32 + lane];
            dot += e1.x*nv.x + e1.y*nv.y + e1.z*nv.z + e1.w*nv.w;
            ss  += e1.x*e1.x + e1.y*e1.y + e1.z*e1.z + e1.w*e1.w;
            nv = s_ns[2 * 32 + lane];
            dot += e2.x*nv.x + e2.y*nv.y + e2.z*nv.z + e2.w*nv.w;
            ss  += e2.x*e2.x + e2.y*e2.y + e2.z*e2.z + e2.w*e2.w;
            nv = s_ns[3 * 32 + lane];
            dot += e3.x*nv.x + e3.y*nv.y + e3.z*nv.z + e3.w*nv.w;
            ss  += e3.x*e3.x + e3.y*e3.y + e3.z*e3.z + e3.w*e3.w;
        }
#pragma unroll
        for (int o = 16; o; o >>= 1) {
            dot += __shfl_xor_sync(0xffffffffu, dot, o);
            ss  += __shfl_xor_sync(0xffffffffu, ss,  o);
        }

        float wt = dot * ((ss > 0.f) ? rsqrtf(ss) : 1e10f);   // |wt| <= 1
        float adjr = fmaxf(__shfl_sync(0xffffffffu, vfull, r << 2) + cb0, 0.f);
        float c = adjr * __expf(wt);
        if (lane == 0) g_c[b * S_LEN + sbase + r] = c;
        csum += c;
        acc0.x = fmaf(c, e0.x, acc0.x); acc0.y = fmaf(c, e0.y, acc0.y);
        acc0.z = fmaf(c, e0.z, acc0.z); acc0.w = fmaf(c, e0.w, acc0.w);
        acc1.x = fmaf(c, e1.x, acc1.x); acc1.y = fmaf(c, e1.y, acc1.y);
        acc1.z = fmaf(c, e1.z, acc1.z); acc1.w = fmaf(c, e1.w, acc1.w);
        acc2.x = fmaf(c, e2.x, acc2.x); acc2.y = fmaf(c, e2.y, acc2.y);
        acc2.z = fmaf(c, e2.z, acc2.z); acc2.w = fmaf(c, e2.w, acc2.w);
        acc3.x = fmaf(c, e3.x, acc3.x); acc3.y = fmaf(c, e3.y, acc3.y);
        acc3.z = fmaf(c, e3.z, acc3.z); acc3.w = fmaf(c, e3.w, acc3.w);
    }

    // ---- block combine (reuse the ring) ----
    __syncthreads();
    float4* sacc = &s_ring[0][0][0];
    sacc[w * 128 + 0 * 32 + lane] = acc0;
    sacc[w * 128 + 1 * 32 + lane] = acc1;
    sacc[w * 128 + 2 * 32 + lane] = acc2;
    sacc[w * 128 + 3 * 32 + lane] = acc3;
    if (lane == 0) s_scs[w] = csum;
    __syncthreads();

    if (tid < 128) {
        float4 v = sacc[tid];
#pragma unroll
        for (int p = 1; p < 8; p++) {
            float4 u = sacc[p * 128 + tid];
            v.x += u.x; v.y += u.y; v.z += u.z; v.w += u.w;
        }
        reinterpret_cast<float4*>(g_pacc)[(b * NS + sp) * 128 + tid] = v;
    }
    if (tid == 0) {
        float z = 0.f;
#pragma unroll
        for (int p = 0; p < 8; p++) z += s_scs[p];
        g_pz[b * NS + sp] = z;
    }

    // ---- last block per batch finalizes ----
    __threadfence();
    __syncthreads();
    if (tid == 0) {
        int v = atomicAdd(&g_done[b], 1);
        s_last = (v == NS - 1);
    }
    __syncthreads();
    if (!s_last) return;
    __threadfence();

    if (tid == 0) {
        float Z = 0.f;
#pragma unroll
        for (int p = 0; p < NS; p++) Z += __ldcg(&g_pz[b * NS + p]);
        s_invZ = 1.f / Z;
    }
    __syncthreads();
    const float invZ = s_invZ;

    float2 s2 = make_float2(0.f, 0.f);
    const float2* pacc2 = reinterpret_cast<const float2*>(g_pacc);
#pragma unroll
    for (int p = 0; p < NS; p++) {
        float2 v = __ldcg(&pacc2[(b * NS + p) * 256 + tid]);
        s2.x += v.x; s2.y += v.y;
    }
    float2 o2; o2.x = s2.x * invZ; o2.y = s2.y * invZ;
    reinterpret_cast<float2*>(out)[b * 256 + tid] = o2;

    for (int s = tid; s < S_LEN; s += 256)
        out[B_SZ * D_SZ + b * S_LEN + s] = __ldcg(&g_c[b * S_LEN + s]) * invZ;
}

// ---------------- launch ----------------
extern "C" void kernel_launch(void* const* d_in, const int* in_sizes, int n_in,
                              void* d_out, int out_size) {
    const float* enc   = (const float*)d_in[0];
    const float* state = (const float*)d_in[1];
    const float* prev  = (const float*)d_in[2];
    const float* W     = (const float*)d_in[3];
    const float* batt  = (const float*)d_in[4];
    const float* cw    = (const float*)d_in[5];
    const float* cb    = (const float*)d_in[6];
    float* out = (float*)d_out;

    k_gemm<<<dim3(64, KSPL), 256>>>(state, W);
    k_main<<<dim3(B_SZ, NS), 256>>>(enc, batt, prev, cw, cb, out);
}